// round 1
// baseline (speedup 1.0000x reference)
#include <cuda_runtime.h>

#define HID 128
#define KX 129          // 128 h-features + 1 agg column
#define M_TILE 128
#define THREADS 256

// Scratch (no cudaMalloc allowed): per-node aggregate + dtype flag
__device__ float g_agg[65536];
__device__ int   g_idx_stride;   // 1 = int32 edges, 2 = int64 edges (read low word)

// ---------------------------------------------------------------------------
// packed fp32x2 helpers (FFMA2 — 2x fp32 FMA throughput on sm_103a)
// ---------------------------------------------------------------------------
__device__ __forceinline__ void fma2(unsigned long long& d,
                                     unsigned long long a,
                                     unsigned long long b) {
    asm("fma.rn.f32x2 %0, %1, %2, %0;" : "+l"(d) : "l"(a), "l"(b));
}
__device__ __forceinline__ unsigned long long dup2(float x) {
    unsigned long long r;
    unsigned xi = __float_as_uint(x);
    asm("mov.b64 %0, {%1, %1};" : "=l"(r) : "r"(xi));
    return r;
}
__device__ __forceinline__ float2 unpk(unsigned long long v) {
    unsigned lo, hi;
    asm("mov.b64 {%0, %1}, %2;" : "=r"(lo), "=r"(hi) : "l"(v));
    return make_float2(__uint_as_float(lo), __uint_as_float(hi));
}
__device__ __forceinline__ float silu(float x) {
    return x * (1.0f / (1.0f + __expf(-x)));
}

// ---------------------------------------------------------------------------
// Kernel 1: zero the aggregate buffer + detect edge index dtype.
// jax.random.randint(..., jnp.int64) silently demotes to int32 when x64 is
// disabled. If the buffer really is int64, every odd 32-bit word is 0
// (indices < 50000). Probe 64 of them.
// ---------------------------------------------------------------------------
__global__ void prep_kernel(const int* __restrict__ edges_i32, int n_nodes, int E) {
    int i = blockIdx.x * blockDim.x + threadIdx.x;
    if (i < n_nodes) g_agg[i] = 0.0f;
    if (blockIdx.x == 0 && threadIdx.x == 0) {
        int probe = E < 64 ? E : 64;
        bool all_zero = true;
        for (int j = 0; j < probe; j++)
            if (edges_i32[2 * j + 1] != 0) { all_zero = false; break; }
        g_idx_stride = all_zero ? 2 : 1;
    }
}

// ---------------------------------------------------------------------------
// Kernel 2: scatter-add distances into g_agg[row[e]]
// ---------------------------------------------------------------------------
__global__ void scatter_kernel(const int* __restrict__ edges_i32,
                               const float* __restrict__ dist, int E) {
    int stride = g_idx_stride;
    int i = blockIdx.x * blockDim.x + threadIdx.x;
    if (i < E) {
        int r = edges_i32[(long long)i * stride];   // little-endian low word
        atomicAdd(&g_agg[r], dist[i]);
    }
}

// ---------------------------------------------------------------------------
// Kernel 3: fused node MLP with residual.
//   x[m, 0:128] = h[node], x[m,128] = agg[node]/100
//   t = silu(x @ W1 + b1);  out = h + t @ W2 + b2
//
// Layout:
//   smem: w1s[129][128] | w2s[128][128] | xt[129][128] (swizzled, reused as tT)
//   xt element (k, m) stored at float index:
//       k*128 + ((m>>2) ^ ((k>>2)&31))*4 + (m&3)
//   -> transpose fill is conflict-free float4 STS; GEMM a-loads are broadcasts.
//
// Thread tile: 8 M-rows x 8 N-cols (4 f32x2 pairs). mt = (tid&1)|(warp<<1),
// nt = (tid>>1)&15 -> W-row LDS.128 conflict-free within each 8-lane phase.
// ---------------------------------------------------------------------------
__global__ void __launch_bounds__(THREADS, 1)
mlp_kernel(const float* __restrict__ h,
           const float* __restrict__ W1, const float* __restrict__ b1,
           const float* __restrict__ W2, const float* __restrict__ b2,
           float* __restrict__ out, int n_nodes, int n_tiles)
{
    extern __shared__ float smem[];
    float* w1s = smem;                         // 129*128
    float* w2s = smem + KX * HID;              // 128*128
    float* xt  = smem + KX * HID + HID * HID;  // 129*128 (swizzled)

    const int tid  = threadIdx.x;
    const int lane = tid & 31;
    const int warp = tid >> 5;
    const int mt   = (tid & 1) | (warp << 1);   // 0..15 (8 M-rows each)
    const int nt   = (tid >> 1) & 15;           // 0..15 (8 N-cols each)

    // biases for this thread's 8 output columns
    float b1r[8], b2r[8];
#pragma unroll
    for (int j = 0; j < 8; j++) {
        b1r[j] = b1[nt * 8 + j];
        b2r[j] = b2[nt * 8 + j];
    }

    // stage weights once per CTA (flat, coalesced float4)
    {
        const float4* g1 = (const float4*)W1;
        float4* s1 = (float4*)w1s;
        for (int i = tid; i < KX * HID / 4; i += THREADS) s1[i] = g1[i];
        const float4* g2 = (const float4*)W2;
        float4* s2 = (float4*)w2s;
        for (int i = tid; i < HID * HID / 4; i += THREADS) s2[i] = g2[i];
    }

    for (int tile = blockIdx.x; tile < n_tiles; tile += gridDim.x) {
        const int base = tile * M_TILE;
        __syncthreads();   // weights staged / previous tile's tT reads done

        // ---- fill xt[k][m] transposed+swizzled from h tile (coalesced) ----
        for (int mg = warp * 4; mg < M_TILE; mg += 32) {
            float4 r[4];
#pragma unroll
            for (int i = 0; i < 4; i++) {
                int gn = base + mg + i;
                r[i] = (gn < n_nodes)
                         ? __ldg((const float4*)&h[gn * HID + lane * 4])
                         : make_float4(0.f, 0.f, 0.f, 0.f);
            }
#pragma unroll
            for (int p = 0; p < 4; p++) {
                int k = lane * 4 + p;                 // k>>2 == lane
                float4 v = make_float4(((const float*)&r[0])[p],
                                       ((const float*)&r[1])[p],
                                       ((const float*)&r[2])[p],
                                       ((const float*)&r[3])[p]);
                int g = (mg >> 2) ^ lane;
                *(float4*)&xt[k * HID + g * 4] = v;
            }
        }
        // agg row k = 128 (swizzle term is 0 since (128>>2)&31 == 0)
        if (tid < 32) {
            int gn = base + tid * 4;
            float4 av;
            av.x = (gn + 0 < n_nodes) ? g_agg[gn + 0] * 0.01f : 0.f;
            av.y = (gn + 1 < n_nodes) ? g_agg[gn + 1] * 0.01f : 0.f;
            av.z = (gn + 2 < n_nodes) ? g_agg[gn + 2] * 0.01f : 0.f;
            av.w = (gn + 3 < n_nodes) ? g_agg[gn + 3] * 0.01f : 0.f;
            *(float4*)&xt[128 * HID + tid * 4] = av;
        }
        __syncthreads();

        // ---- GEMM1: acc[m][np] += x[k][m] * W1[k][n-pair], K = 129 ----
        unsigned long long acc[8][4];
#pragma unroll
        for (int m = 0; m < 8; m++)
#pragma unroll
            for (int n = 0; n < 4; n++) acc[m][n] = 0ull;

        for (int k = 0; k < KX; k++) {
            const float* xrow = xt + k * HID;
            const float* wrow = w1s + k * HID;
            int s = (k >> 2) & 31;
            float4 a0 = *(const float4*)&xrow[((2 * mt) ^ s) * 4];
            float4 a1 = *(const float4*)&xrow[((2 * mt + 1) ^ s) * 4];
            ulonglong2 bb0 = *(const ulonglong2*)&wrow[nt * 8];
            ulonglong2 bb1 = *(const ulonglong2*)&wrow[nt * 8 + 4];
            unsigned long long bp[4] = {bb0.x, bb0.y, bb1.x, bb1.y};
            unsigned long long ad[8];
            ad[0] = dup2(a0.x); ad[1] = dup2(a0.y);
            ad[2] = dup2(a0.z); ad[3] = dup2(a0.w);
            ad[4] = dup2(a1.x); ad[5] = dup2(a1.y);
            ad[6] = dup2(a1.z); ad[7] = dup2(a1.w);
#pragma unroll
            for (int m = 0; m < 8; m++)
#pragma unroll
                for (int n = 0; n < 4; n++) fma2(acc[m][n], ad[m], bp[n]);
        }
        __syncthreads();   // all xt reads done before overwriting as tT

        // ---- bias + silu + transposed store: tT[n][m] over xt buffer ----
#pragma unroll
        for (int j = 0; j < 8; j++) {
            int n = nt * 8 + j;
            float v[8];
#pragma unroll
            for (int m = 0; m < 8; m++) {
                float2 p = unpk(acc[m][j >> 1]);
                float x = ((j & 1) ? p.y : p.x) + b1r[j];
                v[m] = silu(x);
            }
            int s = (n >> 2) & 31;
            *(float4*)&xt[n * HID + ((2 * mt) ^ s) * 4] =
                make_float4(v[0], v[1], v[2], v[3]);
            *(float4*)&xt[n * HID + ((2 * mt + 1) ^ s) * 4] =
                make_float4(v[4], v[5], v[6], v[7]);
        }
        __syncthreads();

        // ---- GEMM2: acc2[m][np] += t[k][m] * W2[k][n-pair], K = 128 ----
        unsigned long long acc2[8][4];
#pragma unroll
        for (int m = 0; m < 8; m++)
#pragma unroll
            for (int n = 0; n < 4; n++) acc2[m][n] = 0ull;

        for (int k = 0; k < HID; k++) {
            const float* xrow = xt + k * HID;
            const float* wrow = w2s + k * HID;
            int s = (k >> 2) & 31;
            float4 a0 = *(const float4*)&xrow[((2 * mt) ^ s) * 4];
            float4 a1 = *(const float4*)&xrow[((2 * mt + 1) ^ s) * 4];
            ulonglong2 bb0 = *(const ulonglong2*)&wrow[nt * 8];
            ulonglong2 bb1 = *(const ulonglong2*)&wrow[nt * 8 + 4];
            unsigned long long bp[4] = {bb0.x, bb0.y, bb1.x, bb1.y};
            unsigned long long ad[8];
            ad[0] = dup2(a0.x); ad[1] = dup2(a0.y);
            ad[2] = dup2(a0.z); ad[3] = dup2(a0.w);
            ad[4] = dup2(a1.x); ad[5] = dup2(a1.y);
            ad[6] = dup2(a1.z); ad[7] = dup2(a1.w);
#pragma unroll
            for (int m = 0; m < 8; m++)
#pragma unroll
                for (int n = 0; n < 4; n++) fma2(acc2[m][n], ad[m], bp[n]);
        }

        // ---- epilogue: out = h + u (residual), coalesced float4 ----
#pragma unroll
        for (int mi = 0; mi < 8; mi++) {
            int gn = base + mt * 8 + mi;
            if (gn < n_nodes) {
                const float4* hp = (const float4*)&h[gn * HID + nt * 8];
                float4 h0 = __ldg(hp), h1 = __ldg(hp + 1);
                float2 p0 = unpk(acc2[mi][0]);
                float2 p1 = unpk(acc2[mi][1]);
                float2 p2 = unpk(acc2[mi][2]);
                float2 p3 = unpk(acc2[mi][3]);
                float4 o0 = make_float4(h0.x + p0.x + b2r[0],
                                        h0.y + p0.y + b2r[1],
                                        h0.z + p1.x + b2r[2],
                                        h0.w + p1.y + b2r[3]);
                float4 o1 = make_float4(h1.x + p2.x + b2r[4],
                                        h1.y + p2.y + b2r[5],
                                        h1.z + p3.x + b2r[6],
                                        h1.w + p3.y + b2r[7]);
                float4* op = (float4*)&out[gn * HID + nt * 8];
                op[0] = o0;
                op[1] = o1;
            }
        }
    }
}

// ---------------------------------------------------------------------------
extern "C" void kernel_launch(void* const* d_in, const int* in_sizes, int n_in,
                              void* d_out, int out_size) {
    const float* h    = (const float*)d_in[0];
    const int*   edg  = (const int*)  d_in[1];   // int32 or int64 (detected)
    const float* dist = (const float*)d_in[2];
    const float* W1   = (const float*)d_in[9];   // W_n1 [129,128]
    const float* b1   = (const float*)d_in[10];  // b_n1 [128]
    const float* W2   = (const float*)d_in[11];  // W_n2 [128,128]
    const float* b2   = (const float*)d_in[12];  // b_n2 [128]
    float* out = (float*)d_out;

    int n_nodes = in_sizes[0] / HID;
    int E       = in_sizes[2];

    int zb = (n_nodes + 255) / 256;
    if (zb < 1) zb = 1;
    prep_kernel<<<zb, 256>>>(edg, n_nodes, E);
    scatter_kernel<<<(E + 255) / 256, 256>>>(edg, dist, E);

    const int smem_bytes = (KX * HID + HID * HID + KX * HID) * (int)sizeof(float);
    cudaFuncSetAttribute(mlp_kernel,
                         cudaFuncAttributeMaxDynamicSharedMemorySize, smem_bytes);
    int sms = 148;
    cudaDeviceGetAttribute(&sms, cudaDevAttrMultiProcessorCount, 0);
    int n_tiles = (n_nodes + M_TILE - 1) / M_TILE;
    int grid = n_tiles < sms ? n_tiles : sms;
    mlp_kernel<<<grid, THREADS, smem_bytes>>>(h, W1, b1, W2, b2, out,
                                              n_nodes, n_tiles);
}